// round 10
// baseline (speedup 1.0000x reference)
#include <cuda_runtime.h>
#include <cuda_fp16.h>
#include <cstdint>
#include <math.h>

#define M_DIM 16384
#define K_DIM 768
#define N_DIM 3072

// ---------------- scratch (no cudaMalloc allowed) ----------------
__device__ uint16_t g_A[M_DIM * K_DIM];    // fp16 bits, LN output
__device__ uint16_t g_B[N_DIM * K_DIM];    // fp16 bits, W transposed [N, K]

// ---------------- helpers ----------------
__device__ __forceinline__ uint32_t smem_u32(const void* p) {
    uint32_t a;
    asm("{ .reg .u64 t; cvta.to.shared.u64 t, %1; cvt.u32.u64 %0, t; }" : "=r"(a) : "l"(p));
    return a;
}
__device__ __forceinline__ uint32_t pack_h2(float lo, float hi) {
    uint32_t r;
    asm("cvt.rn.f16x2.f32 %0, %1, %2;" : "=r"(r) : "f"(hi), "f"(lo));
    return r;
}
__device__ __forceinline__ void cp_async16(uint32_t dst, const void* src) {
    asm volatile("cp.async.cg.shared.global [%0], [%1], 16;"
                 :: "r"(dst), "l"(__cvta_generic_to_global(src)) : "memory");
}
#define CP_COMMIT() asm volatile("cp.async.commit_group;" ::: "memory")
#define CP_WAIT(n)  asm volatile("cp.async.wait_group %0;" :: "n"(n) : "memory")

__device__ __forceinline__ void ldmatrix_x4(uint32_t* r, uint32_t addr) {
    asm volatile("ldmatrix.sync.aligned.m8n8.x4.shared.b16 {%0,%1,%2,%3}, [%4];"
                 : "=r"(r[0]), "=r"(r[1]), "=r"(r[2]), "=r"(r[3]) : "r"(addr));
}
__device__ __forceinline__ void mma_f16(float* d, const uint32_t* a,
                                        uint32_t b0, uint32_t b1) {
    asm volatile(
        "mma.sync.aligned.m16n8k16.row.col.f32.f16.f16.f32 "
        "{%0,%1,%2,%3}, {%4,%5,%6,%7}, {%8,%9}, {%0,%1,%2,%3};"
        : "+f"(d[0]), "+f"(d[1]), "+f"(d[2]), "+f"(d[3])
        : "r"(a[0]), "r"(a[1]), "r"(a[2]), "r"(a[3]), "r"(b0), "r"(b1));
}
__device__ __forceinline__ float gelu_exact(float h) {
    return 0.5f * h * (1.0f + erff(h * 0.70710678118654752f));
}

// ---------------------------------------------------------------------------
// Kernel 1: LayerNorm -> fp16 (unchanged)
// ---------------------------------------------------------------------------
__global__ __launch_bounds__(256) void ln_h_kernel(
    const float* __restrict__ x,
    const float* __restrict__ gamma,
    const float* __restrict__ beta)
{
    const int tid = threadIdx.x;
    const int rloc = tid >> 6;
    const int t = tid & 63;
    const int row = blockIdx.x * 4 + rloc;
    const float4* xr = (const float4*)(x + (size_t)row * K_DIM);

    float4 v[3];
    #pragma unroll
    for (int j = 0; j < 3; j++) v[j] = xr[t + 64 * j];

    float s = 0.0f, s2 = 0.0f;
    #pragma unroll
    for (int j = 0; j < 3; j++) {
        s  += v[j].x + v[j].y + v[j].z + v[j].w;
        s2 += v[j].x * v[j].x + v[j].y * v[j].y + v[j].z * v[j].z + v[j].w * v[j].w;
    }
    #pragma unroll
    for (int off = 16; off > 0; off >>= 1) {
        s  += __shfl_xor_sync(0xffffffffu, s,  off);
        s2 += __shfl_xor_sync(0xffffffffu, s2, off);
    }
    __shared__ float red[4][2][2];
    const int wir = (t >> 5);
    if ((t & 31) == 0) { red[rloc][wir][0] = s; red[rloc][wir][1] = s2; }
    __syncthreads();
    s  = red[rloc][0][0] + red[rloc][1][0];
    s2 = red[rloc][0][1] + red[rloc][1][1];

    const float inv_n = 1.0f / (float)K_DIM;
    const float mu  = s * inv_n;
    const float var = fmaxf(s2 * inv_n - mu * mu, 0.0f);
    const float rstd = rsqrtf(var + 1e-12f);

    uint2* outr = (uint2*)(g_A + (size_t)row * K_DIM);
    #pragma unroll
    for (int j = 0; j < 3; j++) {
        const float4 g = ((const float4*)gamma)[t + 64 * j];
        const float4 be = ((const float4*)beta)[t + 64 * j];
        uint2 o;
        o.x = pack_h2((v[j].x - mu) * rstd * g.x + be.x,
                      (v[j].y - mu) * rstd * g.y + be.y);
        o.y = pack_h2((v[j].z - mu) * rstd * g.z + be.z,
                      (v[j].w - mu) * rstd * g.w + be.w);
        outr[t + 64 * j] = o;
    }
}

// ---------------------------------------------------------------------------
// Kernel 2: transpose W [K,N] -> [N,K] fp16 (unchanged)
// ---------------------------------------------------------------------------
__global__ __launch_bounds__(256) void wt_h_kernel(const float* __restrict__ W)
{
    __shared__ float tile[64][33];
    const int tx = threadIdx.x, ty = threadIdx.y;
    const int n0 = blockIdx.x * 32, k0 = blockIdx.y * 64;

    #pragma unroll
    for (int j = 0; j < 8; j++)
        tile[ty + 8 * j][tx] = W[(size_t)(k0 + ty + 8 * j) * N_DIM + n0 + tx];
    __syncthreads();

    uint4 o;
    o.x = pack_h2(tile[ty * 8 + 0][tx], tile[ty * 8 + 1][tx]);
    o.y = pack_h2(tile[ty * 8 + 2][tx], tile[ty * 8 + 3][tx]);
    o.z = pack_h2(tile[ty * 8 + 4][tx], tile[ty * 8 + 5][tx]);
    o.w = pack_h2(tile[ty * 8 + 6][tx], tile[ty * 8 + 7][tx]);
    *(uint4*)&g_B[(size_t)(n0 + tx) * K_DIM + k0 + ty * 8] = o;
}

// ---------------------------------------------------------------------------
// Kernel 3: INTRA-CTA HYBRID GEMM.
// Tensor: cols 0..111 of the 128-wide tile (8 warps x 32x56, f32-acc HMMA).
// HFMA2:  cols 112..127 (each warp 16 rows x 16 cols, pairwise f16x2 acc,
//         promoted to fp32 every K=32 step).
// ---------------------------------------------------------------------------
#define BM 128
#define BN 128
#define BK 32
#define ROWH 40
#define NSTEP 24
#define NSTAGE 3
#define NT 7                 // n-tiles (8 cols each) per tensor warp

__global__ __launch_bounds__(256, 2) void gemm_hy_kernel(
    const float* __restrict__ bias, float* __restrict__ C)
{
    __shared__ uint16_t As[NSTAGE][BM * ROWH];
    __shared__ uint16_t Bs[NSTAGE][BN * ROWH];

    const int tid = threadIdx.x;
    const int wid = tid >> 5, lane = tid & 31;
    const int bn = blockIdx.x * BN;
    const int bm = blockIdx.y * BM;
    // SMSP-balanced mapping: SMSP k hosts wid k (wn=0) and wid k+4 (wn=56)
    const int wm = (wid & 3) * 32;
    const int wn = ((wid >> 2) & 1) * 56;

    float acc[2][NT][4];
    #pragma unroll
    for (int mt = 0; mt < 2; mt++)
        #pragma unroll
        for (int nt = 0; nt < NT; nt++)
            #pragma unroll
            for (int q = 0; q < 4; q++) acc[mt][nt][q] = 0.0f;

    // FFMA region state: warp wid -> rows [wid*16, wid*16+16), cols 112..127
    const int fr0 = wid * 16 + (lane >> 3) * 4;     // 4 rows
    const int fc0 = 112 + (lane & 7) * 2;           // 2 cols
    float accf[4][2];
    #pragma unroll
    for (int r = 0; r < 4; r++) { accf[r][0] = 0.0f; accf[r][1] = 0.0f; }

    const uint32_t sA0 = smem_u32(&As[0][0]);
    const uint32_t sB0 = smem_u32(&Bs[0][0]);
    const uint32_t stageA = (uint32_t)(BM * ROWH * 2);
    const uint32_t stageB = (uint32_t)(BN * ROWH * 2);

    const int r_ld  = tid >> 2;
    const int c_ld  = (tid & 3) * 8;

    auto load_stage = [&](int st, int step) {
        const int k0 = step * BK;
        #pragma unroll
        for (int i = 0; i < 2; i++) {
            const int r = r_ld + i * 64;
            const uint32_t soff = (uint32_t)(r * ROWH + c_ld) * 2;
            cp_async16(sA0 + st * stageA + soff,
                       g_A + (size_t)(bm + r) * K_DIM + k0 + c_ld);
            cp_async16(sB0 + st * stageB + soff,
                       g_B + (size_t)(bn + r) * K_DIM + k0 + c_ld);
        }
        CP_COMMIT();
    };

    load_stage(0, 0);
    load_stage(1, 1);

    for (int step = 0; step < NSTEP; step++) {
        const int st = step % NSTAGE;
        if (step < NSTEP - 1) { CP_WAIT(1); } else { CP_WAIT(0); }
        __syncthreads();

        // ---------------- tensor part: cols [wn, wn+56) ----------------
        #pragma unroll
        for (int kk = 0; kk < 2; kk++) {
            const int chunk = kk * 2 + (lane >> 4);
            uint32_t a[2][4];
            #pragma unroll
            for (int mt = 0; mt < 2; mt++) {
                const int row = wm + mt * 16 + (lane & 15);
                ldmatrix_x4(a[mt], sA0 + st * stageA
                                   + (uint32_t)(row * ROWH) * 2 + chunk * 16);
            }
            #pragma unroll
            for (int g = 0; g < 4; g++) {
                uint32_t b4[4];
                const int row = wn + g * 16 + (lane & 15);
                ldmatrix_x4(b4, sB0 + st * stageB
                                + (uint32_t)(row * ROWH) * 2 + chunk * 16);
                #pragma unroll
                for (int mt = 0; mt < 2; mt++) {
                    mma_f16(acc[mt][2 * g], a[mt], b4[0], b4[2]);
                    if (2 * g + 1 < NT)
                        mma_f16(acc[mt][2 * g + 1], a[mt], b4[1], b4[3]);
                }
            }
        }

        // ---------------- HFMA2 part: cols 112..127 ----------------
        {
            __half2 acc2[4][2];
            #pragma unroll
            for (int r = 0; r < 4; r++) {
                acc2[r][0] = __float2half2_rn(0.0f);
                acc2[r][1] = __float2half2_rn(0.0f);
            }
            const uint16_t* AsS = &As[0][0] + st * (BM * ROWH);
            const uint16_t* BsS = &Bs[0][0] + st * (BN * ROWH);
            #pragma unroll
            for (int ch = 0; ch < 4; ch++) {
                const __half2* b0 = (const __half2*)(BsS + fc0 * ROWH + ch * 8);
                const __half2* b1 = (const __half2*)(BsS + (fc0 + 1) * ROWH + ch * 8);
                __half2 B0[4], B1[4];
                #pragma unroll
                for (int p = 0; p < 4; p++) { B0[p] = b0[p]; B1[p] = b1[p]; }
                #pragma unroll
                for (int r = 0; r < 4; r++) {
                    const __half2* av = (const __half2*)(AsS + (fr0 + r) * ROWH + ch * 8);
                    #pragma unroll
                    for (int p = 0; p < 4; p++) {
                        __half2 a2 = av[p];
                        acc2[r][0] = __hfma2(a2, B0[p], acc2[r][0]);
                        acc2[r][1] = __hfma2(a2, B1[p], acc2[r][1]);
                    }
                }
            }
            // promote window (K=32) to fp32
            #pragma unroll
            for (int r = 0; r < 4; r++) {
                float2 p0 = __half22float2(acc2[r][0]);
                float2 p1 = __half22float2(acc2[r][1]);
                accf[r][0] += p0.x + p0.y;
                accf[r][1] += p1.x + p1.y;
            }
        }

        if (step + 2 < NSTEP) load_stage((step + 2) % NSTAGE, step + 2);
    }

    // ---------------- epilogue: bias + exact erf GELU ----------------
    // tensor cols
    const int r0 = bm + wm + (lane >> 2);
    const int c0 = bn + wn + (lane & 3) * 2;
    #pragma unroll
    for (int mt = 0; mt < 2; mt++) {
        #pragma unroll
        for (int nt = 0; nt < NT; nt++) {
            const int col = c0 + nt * 8;
            const float b0 = __ldg(&bias[col]), b1 = __ldg(&bias[col + 1]);
            #pragma unroll
            for (int half = 0; half < 2; half++) {
                const int row = r0 + mt * 16 + half * 8;
                float2 o;
                o.x = gelu_exact(acc[mt][nt][half * 2 + 0] + b0);
                o.y = gelu_exact(acc[mt][nt][half * 2 + 1] + b1);
                *(float2*)&C[(size_t)row * N_DIM + col] = o;
            }
        }
    }
    // FFMA cols
    {
        const int col = bn + fc0;
        const float b0 = __ldg(&bias[col]), b1 = __ldg(&bias[col + 1]);
        #pragma unroll
        for (int r = 0; r < 4; r++) {
            const int row = bm + fr0 + r;
            float2 o;
            o.x = gelu_exact(accf[r][0] + b0);
            o.y = gelu_exact(accf[r][1] + b1);
            *(float2*)&C[(size_t)row * N_DIM + col] = o;
        }
    }
}

// ---------------------------------------------------------------------------
extern "C" void kernel_launch(void* const* d_in, const int* in_sizes, int n_in,
                              void* d_out, int out_size)
{
    const float* x     = (const float*)d_in[0];
    const float* gamma = (const float*)d_in[1];
    const float* beta  = (const float*)d_in[2];
    const float* W     = (const float*)d_in[3];
    const float* b     = (const float*)d_in[4];
    float* out = (float*)d_out;

    ln_h_kernel<<<M_DIM / 4, 256>>>(x, gamma, beta);
    wt_h_kernel<<<dim3(N_DIM / 32, K_DIM / 64), dim3(32, 8)>>>(W);
    gemm_hy_kernel<<<dim3(N_DIM / BN, M_DIM / BM), 256>>>(b, out);
}

// round 11
// speedup vs baseline: 1.3769x; 1.3769x over previous
#include <cuda_runtime.h>
#include <cuda_fp16.h>
#include <cstdint>
#include <math.h>

#define M_DIM 16384
#define K_DIM 768
#define N_DIM 3072

// ---------------- scratch (no cudaMalloc allowed) ----------------
__device__ uint16_t g_A[M_DIM * K_DIM];    // fp16 bits, LN output
__device__ uint16_t g_B[N_DIM * K_DIM];    // fp16 bits, W transposed [N, K]
__device__ int g_cnt_a[M_DIM / 128];       // LN producer counters (zero-init)

// ---------------- helpers ----------------
__device__ __forceinline__ uint32_t smem_u32(const void* p) {
    uint32_t a;
    asm("{ .reg .u64 t; cvta.to.shared.u64 t, %1; cvt.u32.u64 %0, t; }" : "=r"(a) : "l"(p));
    return a;
}
__device__ __forceinline__ uint32_t pack_h2(float lo, float hi) {
    uint32_t r;
    asm("cvt.rn.f16x2.f32 %0, %1, %2;" : "=r"(r) : "f"(hi), "f"(lo));
    return r;
}
__device__ __forceinline__ void cp_async16(uint32_t dst, const void* src) {
    asm volatile("cp.async.cg.shared.global [%0], [%1], 16;"
                 :: "r"(dst), "l"(__cvta_generic_to_global(src)) : "memory");
}
#define CP_COMMIT() asm volatile("cp.async.commit_group;" ::: "memory")
#define CP_WAIT(n)  asm volatile("cp.async.wait_group %0;" :: "n"(n) : "memory")

__device__ __forceinline__ void ldmatrix_x4(uint32_t* r, uint32_t addr) {
    asm volatile("ldmatrix.sync.aligned.m8n8.x4.shared.b16 {%0,%1,%2,%3}, [%4];"
                 : "=r"(r[0]), "=r"(r[1]), "=r"(r[2]), "=r"(r[3]) : "r"(addr));
}
__device__ __forceinline__ void mma_f16(float* d, const uint32_t* a,
                                        uint32_t b0, uint32_t b1) {
    asm volatile(
        "mma.sync.aligned.m16n8k16.row.col.f32.f16.f16.f32 "
        "{%0,%1,%2,%3}, {%4,%5,%6,%7}, {%8,%9}, {%0,%1,%2,%3};"
        : "+f"(d[0]), "+f"(d[1]), "+f"(d[2]), "+f"(d[3])
        : "r"(a[0]), "r"(a[1]), "r"(a[2]), "r"(a[3]), "r"(b0), "r"(b1));
}
__device__ __forceinline__ float gelu_exact(float h) {
    return 0.5f * h * (1.0f + erff(h * 0.70710678118654752f));
}

// ---------------------------------------------------------------------------
// Kernel 1: transpose W [K,N] -> [N,K] fp16 (unchanged from R7)
// ---------------------------------------------------------------------------
__global__ __launch_bounds__(256) void wt_h_kernel(const float* __restrict__ W)
{
    __shared__ float tile[64][33];
    const int tx = threadIdx.x, ty = threadIdx.y;
    const int n0 = blockIdx.x * 32, k0 = blockIdx.y * 64;

    #pragma unroll
    for (int j = 0; j < 8; j++)
        tile[ty + 8 * j][tx] = W[(size_t)(k0 + ty + 8 * j) * N_DIM + n0 + tx];
    __syncthreads();

    uint4 o;
    o.x = pack_h2(tile[ty * 8 + 0][tx], tile[ty * 8 + 1][tx]);
    o.y = pack_h2(tile[ty * 8 + 2][tx], tile[ty * 8 + 3][tx]);
    o.z = pack_h2(tile[ty * 8 + 4][tx], tile[ty * 8 + 5][tx]);
    o.w = pack_h2(tile[ty * 8 + 6][tx], tile[ty * 8 + 7][tx]);
    *(uint4*)&g_B[(size_t)(n0 + tx) * K_DIM + k0 + ty * 8] = o;
}

// ---------------------------------------------------------------------------
// Kernel 2: FUSED LN + GEMM.
// bid -> (bx = bid%24 [N block], by = bid/24 [M block]).
// bx<8: LN-producer for rows [bm+bx*16, bm+bx*16+16), then counter++.
// All: spin until cnt[by]>=8, then R7 GEMM mainloop (unchanged).
// ---------------------------------------------------------------------------
#define BM 128
#define BN 128
#define BK 32
#define ROWH 40
#define NSTEP 24
#define NSTAGE 3
#define NBX (N_DIM / BN)     // 24

__global__ __launch_bounds__(256, 2) void gemm_fused_kernel(
    const float* __restrict__ x,
    const float* __restrict__ gamma,
    const float* __restrict__ beta,
    const float* __restrict__ bias,
    float* __restrict__ C)
{
    __shared__ uint16_t As[NSTAGE][BM * ROWH];
    __shared__ uint16_t Bs[NSTAGE][BN * ROWH];
    __shared__ float lred[4][2][2];

    const int tid = threadIdx.x;
    const int bid = blockIdx.x;
    const int bx = bid % NBX;
    const int by = bid / NBX;
    const int bn = bx * BN;
    const int bm = by * BM;

    // ---------------- LN producer phase (bx < 8) ----------------
    if (bx < 8) {
        const int t = tid & 63;
        const int rl = tid >> 6;
        const int wir = t >> 5;
        #pragma unroll 1
        for (int p = 0; p < 4; p++) {
            const int row = bm + bx * 16 + p * 4 + rl;
            const float4* xr = (const float4*)(x + (size_t)row * K_DIM);
            float4 v[3];
            #pragma unroll
            for (int j = 0; j < 3; j++) v[j] = xr[t + 64 * j];

            float s = 0.0f, s2 = 0.0f;
            #pragma unroll
            for (int j = 0; j < 3; j++) {
                s  += v[j].x + v[j].y + v[j].z + v[j].w;
                s2 += v[j].x * v[j].x + v[j].y * v[j].y
                    + v[j].z * v[j].z + v[j].w * v[j].w;
            }
            #pragma unroll
            for (int off = 16; off > 0; off >>= 1) {
                s  += __shfl_xor_sync(0xffffffffu, s,  off);
                s2 += __shfl_xor_sync(0xffffffffu, s2, off);
            }
            __syncthreads();   // protect lred reuse across passes
            if ((t & 31) == 0) { lred[rl][wir][0] = s; lred[rl][wir][1] = s2; }
            __syncthreads();
            s  = lred[rl][0][0] + lred[rl][1][0];
            s2 = lred[rl][0][1] + lred[rl][1][1];

            const float inv_n = 1.0f / (float)K_DIM;
            const float mu  = s * inv_n;
            const float var = fmaxf(s2 * inv_n - mu * mu, 0.0f);
            const float rstd = rsqrtf(var + 1e-12f);

            uint2* outr = (uint2*)(g_A + (size_t)row * K_DIM);
            #pragma unroll
            for (int j = 0; j < 3; j++) {
                const float4 g = ((const float4*)gamma)[t + 64 * j];
                const float4 be = ((const float4*)beta)[t + 64 * j];
                uint2 o;
                o.x = pack_h2((v[j].x - mu) * rstd * g.x + be.x,
                              (v[j].y - mu) * rstd * g.y + be.y);
                o.y = pack_h2((v[j].z - mu) * rstd * g.z + be.z,
                              (v[j].w - mu) * rstd * g.w + be.w);
                outr[t + 64 * j] = o;
            }
        }
        __threadfence();
        __syncthreads();
        if (tid == 0) atomicAdd(&g_cnt_a[by], 1);
    }

    // ---------------- wait for this M-block's LN ----------------
    if (tid == 0) {
        while (*(volatile int*)&g_cnt_a[by] < 8) { }
        __threadfence();
    }
    __syncthreads();

    // ---------------- GEMM (identical to R7) ----------------
    const int wid = tid >> 5, lane = tid & 31;
    const int wm = (wid >> 1) * 32;
    const int wn = (wid & 1) * 64;

    float acc[2][8][4];
    #pragma unroll
    for (int mt = 0; mt < 2; mt++)
        #pragma unroll
        for (int nt = 0; nt < 8; nt++)
            #pragma unroll
            for (int q = 0; q < 4; q++) acc[mt][nt][q] = 0.0f;

    const uint32_t sA0 = smem_u32(&As[0][0]);
    const uint32_t sB0 = smem_u32(&Bs[0][0]);
    const uint32_t stageA = (uint32_t)(BM * ROWH * 2);
    const uint32_t stageB = (uint32_t)(BN * ROWH * 2);

    const int r_ld  = tid >> 2;
    const int c_ld  = (tid & 3) * 8;

    auto load_stage = [&](int st, int step) {
        const int k0 = step * BK;
        #pragma unroll
        for (int i = 0; i < 2; i++) {
            const int r = r_ld + i * 64;
            const uint32_t soff = (uint32_t)(r * ROWH + c_ld) * 2;
            cp_async16(sA0 + st * stageA + soff,
                       g_A + (size_t)(bm + r) * K_DIM + k0 + c_ld);
            cp_async16(sB0 + st * stageB + soff,
                       g_B + (size_t)(bn + r) * K_DIM + k0 + c_ld);
        }
        CP_COMMIT();
    };

    load_stage(0, 0);
    load_stage(1, 1);

    for (int step = 0; step < NSTEP; step++) {
        const int st = step % NSTAGE;
        if (step < NSTEP - 1) { CP_WAIT(1); } else { CP_WAIT(0); }
        __syncthreads();

        #pragma unroll
        for (int kk = 0; kk < 2; kk++) {
            const int chunk = kk * 2 + (lane >> 4);
            uint32_t a[2][4];
            #pragma unroll
            for (int mt = 0; mt < 2; mt++) {
                const int row = wm + mt * 16 + (lane & 15);
                ldmatrix_x4(a[mt], sA0 + st * stageA
                                   + (uint32_t)(row * ROWH) * 2 + chunk * 16);
            }
            uint32_t b[4][4];
            #pragma unroll
            for (int g = 0; g < 4; g++) {
                const int row = wn + g * 16 + (lane & 15);
                ldmatrix_x4(b[g], sB0 + st * stageB
                                  + (uint32_t)(row * ROWH) * 2 + chunk * 16);
            }
            #pragma unroll
            for (int mt = 0; mt < 2; mt++)
                #pragma unroll
                for (int nt = 0; nt < 8; nt++)
                    mma_f16(acc[mt][nt], a[mt],
                            b[nt >> 1][nt & 1], b[nt >> 1][2 + (nt & 1)]);
        }

        if (step + 2 < NSTEP) load_stage((step + 2) % NSTAGE, step + 2);
    }

    // epilogue: bias + exact erf GELU
    const int r0 = bm + wm + (lane >> 2);
    const int c0 = bn + wn + (lane & 3) * 2;
    #pragma unroll
    for (int mt = 0; mt < 2; mt++) {
        #pragma unroll
        for (int nt = 0; nt < 8; nt++) {
            const int col = c0 + nt * 8;
            const float b0 = __ldg(&bias[col]), b1 = __ldg(&bias[col + 1]);
            #pragma unroll
            for (int half = 0; half < 2; half++) {
                const int row = r0 + mt * 16 + half * 8;
                float2 o;
                o.x = gelu_exact(acc[mt][nt][half * 2 + 0] + b0);
                o.y = gelu_exact(acc[mt][nt][half * 2 + 1] + b1);
                *(float2*)&C[(size_t)row * N_DIM + col] = o;
            }
        }
    }
}

// ---------------------------------------------------------------------------
extern "C" void kernel_launch(void* const* d_in, const int* in_sizes, int n_in,
                              void* d_out, int out_size)
{
    const float* x     = (const float*)d_in[0];
    const float* gamma = (const float*)d_in[1];
    const float* beta  = (const float*)d_in[2];
    const float* W     = (const float*)d_in[3];
    const float* b     = (const float*)d_in[4];
    float* out = (float*)d_out;

    wt_h_kernel<<<dim3(N_DIM / 32, K_DIM / 64), dim3(32, 8)>>>(W);
    gemm_fused_kernel<<<(N_DIM / BN) * (M_DIM / BM), 256>>>(x, gamma, beta, b, out);
}